// round 2
// baseline (speedup 1.0000x reference)
#include <cuda_runtime.h>
#include <math.h>

#define NPTS 8192
#define DIM 32
#define NT 16            // k-pair steps (DIM/2)
#define JT 32            // owner rows per block
#define IT 128           // streamed cols per tile
#define NTHREADS 256

__device__ float g_norm[2][NPTS];     // [0]=P norms, [1]=Q norms
__device__ float g_rho_sq[2][NPTS];   // [0]: Y=Q, [1]: Y=P
__device__ int   g_kp[2][NPTS];

// ---- packed f32x2 helpers -------------------------------------------------
__device__ __forceinline__ void ffma2(unsigned long long& d,
                                      unsigned long long a,
                                      unsigned long long b) {
    asm("fma.rn.f32x2 %0, %1, %2, %0;" : "+l"(d) : "l"(a), "l"(b));
}
__device__ __forceinline__ float2 unpk(unsigned long long v) {
    float2 r;
    asm("mov.b64 {%0, %1}, %2;" : "=f"(r.x), "=f"(r.y) : "l"(v));
    return r;
}
__device__ __forceinline__ void ins4(float& m0, float& m1, float& m2, float& m3, float s) {
    if (s < m3) {
        m3 = s;
        float t;
        if (m3 < m2) { t = m2; m2 = m3; m3 = t; }
        if (m2 < m1) { t = m1; m1 = m2; m2 = t; }
        if (m1 < m0) { t = m0; m0 = m1; m1 = t; }
    }
}

// ---- norms + zero counts --------------------------------------------------
__global__ void norms_kernel(const float* __restrict__ P, const float* __restrict__ Q) {
    int t = blockIdx.x * blockDim.x + threadIdx.x;
    if (t >= 2 * NPTS) return;
    int w = (t >= NPTS);
    int row = w ? t - NPTS : t;
    const float4* r4 = (const float4*)((w ? Q : P) + (size_t)row * DIM);
    float s = 0.f;
#pragma unroll
    for (int i = 0; i < DIM / 4; i++) {
        float4 v = r4[i];
        s = fmaf(v.x, v.x, s);
        s = fmaf(v.y, v.y, s);
        s = fmaf(v.z, v.z, s);
        s = fmaf(v.w, v.w, s);
    }
    g_norm[w][row] = s;
    g_kp[w][row] = 0;
}

// ---- main tiled pass ------------------------------------------------------
// MODE 0: knn (Y vs Y, blockIdx.z = m; m=0 -> Y=Q, m=1 -> Y=P), writes g_rho_sq
// MODE 1: merged count pass over D(P,Q): row counts -> g_kp[1], col counts -> g_kp[0]
template <int MODE>
__global__ __launch_bounds__(NTHREADS, 2)
void pass_kernel(const float* __restrict__ P, const float* __restrict__ Q) {
    __shared__ __align__(16) float2 smX[NT * IT];   // 16 KB, [t][i] k-pairs
    __shared__ __align__(16) float2 smY[NT * JT];   //  4 KB, [t][j] k-pairs
    __shared__ float smNB[IT];
    __shared__ float smRB[IT];

    const int id = threadIdx.x;
    const int tx = id & 15;    // row group: 2 rows
    const int ty = id >> 4;    // col group: 8 cols

    const int m = (MODE == 0) ? blockIdx.z : 0;

    const float* __restrict__ Yrow = (MODE == 0) ? (m ? P : Q) : P;
    const float* __restrict__ Xrow = (MODE == 0) ? Yrow : Q;
    const float* __restrict__ nYv  = (MODE == 0) ? (m ? g_norm[0] : g_norm[1]) : g_norm[0];
    const float* __restrict__ nXv  = (MODE == 0) ? nYv : g_norm[1];

    const int j0 = blockIdx.x * JT;

    // fill Y tile once (k-pair major)
    if (id < 64) {
        int r = id & 31, h = id >> 5;
        const float4* src = (const float4*)(Yrow + (size_t)(j0 + r) * DIM + h * 16);
#pragma unroll
        for (int q = 0; q < 4; q++) {
            float4 v = src[q];
            int t0 = h * 8 + 2 * q;
            smY[t0 * JT + r]       = make_float2(v.x, v.y);
            smY[(t0 + 1) * JT + r] = make_float2(v.z, v.w);
        }
    }

    const int r0 = j0 + tx * 2;
    const float na0 = nYv[r0], na1 = nYv[r0 + 1];

    float a00 = 3.4e38f, a01 = 3.4e38f, a02 = 3.4e38f, a03 = 3.4e38f;   // top4 row0
    float b00 = 3.4e38f, b01 = 3.4e38f, b02 = 3.4e38f, b03 = 3.4e38f;   // top4 row1
    int cntA0 = 0, cntA1 = 0;
    float rA0 = 0.f, rA1 = 0.f;
    if (MODE == 1) { rA0 = g_rho_sq[1][r0]; rA1 = g_rho_sq[1][r0 + 1]; }

    for (int ib = 0; ib < NPTS; ib += IT) {
        __syncthreads();
        // fill streamed X tile (k-pair major) + norms (+ rhoB for counts)
        {
            int i = id & 127, h = id >> 7;
            const float4* src = (const float4*)(Xrow + (size_t)(ib + i) * DIM + h * 16);
#pragma unroll
            for (int q = 0; q < 4; q++) {
                float4 v = src[q];
                int t0 = h * 8 + 2 * q;
                smX[t0 * IT + i]       = make_float2(v.x, v.y);
                smX[(t0 + 1) * IT + i] = make_float2(v.z, v.w);
            }
            if (id < IT) smNB[id] = nXv[ib + id];
            else if (MODE == 1) smRB[id - IT] = g_rho_sq[0][ib + id - IT];
        }
        __syncthreads();

        unsigned long long acc[16];
#pragma unroll
        for (int e = 0; e < 16; e++) acc[e] = 0ull;

#pragma unroll 4
        for (int t = 0; t < NT; t++) {
            ulonglong2 yp = *(const ulonglong2*)&smY[t * JT + tx * 2];
            const ulonglong2* xb = (const ulonglong2*)&smX[t * IT + ty * 8];
            ulonglong2 x0 = xb[0], x1 = xb[1], x2 = xb[2], x3 = xb[3];
            unsigned long long xp0 = x0.x, xp1 = x0.y, xp2 = x1.x, xp3 = x1.y;
            unsigned long long xp4 = x2.x, xp5 = x2.y, xp6 = x3.x, xp7 = x3.y;
            ffma2(acc[0], yp.x, xp0);  ffma2(acc[1], yp.x, xp1);
            ffma2(acc[2], yp.x, xp2);  ffma2(acc[3], yp.x, xp3);
            ffma2(acc[4], yp.x, xp4);  ffma2(acc[5], yp.x, xp5);
            ffma2(acc[6], yp.x, xp6);  ffma2(acc[7], yp.x, xp7);
            ffma2(acc[8], yp.y, xp0);  ffma2(acc[9], yp.y, xp1);
            ffma2(acc[10], yp.y, xp2); ffma2(acc[11], yp.y, xp3);
            ffma2(acc[12], yp.y, xp4); ffma2(acc[13], yp.y, xp5);
            ffma2(acc[14], yp.y, xp6); ffma2(acc[15], yp.y, xp7);
        }

        // epilogue: distances for the 2x8 block
        float nb[8];
        {
            float4 u = *(const float4*)&smNB[ty * 8];
            float4 v = *(const float4*)&smNB[ty * 8 + 4];
            nb[0] = u.x; nb[1] = u.y; nb[2] = u.z; nb[3] = u.w;
            nb[4] = v.x; nb[5] = v.y; nb[6] = v.z; nb[7] = v.w;
        }
        float s0[8], s1[8];
#pragma unroll
        for (int c = 0; c < 8; c++) {
            float2 p = unpk(acc[c]);
            s0[c] = fmaf(p.x + p.y, -2.f, na0 + nb[c]);
            float2 q = unpk(acc[8 + c]);
            s1[c] = fmaf(q.x + q.y, -2.f, na1 + nb[c]);
        }

        if (MODE == 0) {
#pragma unroll
            for (int c = 0; c < 8; c++) {
                ins4(a00, a01, a02, a03, s0[c]);
                ins4(b00, b01, b02, b03, s1[c]);
            }
        } else {
            float rb[8];
            {
                float4 u = *(const float4*)&smRB[ty * 8];
                float4 v = *(const float4*)&smRB[ty * 8 + 4];
                rb[0] = u.x; rb[1] = u.y; rb[2] = u.z; rb[3] = u.w;
                rb[4] = v.x; rb[5] = v.y; rb[6] = v.z; rb[7] = v.w;
            }
            unsigned int p0 = 0, p1 = 0;
#pragma unroll
            for (int c = 0; c < 4; c++) {
                unsigned int bc = (s0[c] <= rb[c] ? 1u : 0u) + (s1[c] <= rb[c] ? 1u : 0u);
                p0 += bc << (8 * c);
                unsigned int bd = (s0[c + 4] <= rb[c + 4] ? 1u : 0u) + (s1[c + 4] <= rb[c + 4] ? 1u : 0u);
                p1 += bd << (8 * c);
            }
#pragma unroll
            for (int c = 0; c < 8; c++) {
                cntA0 += (s0[c] <= rA0) ? 1 : 0;
                cntA1 += (s1[c] <= rA1) ? 1 : 0;
            }
            // reduce col counts across the 16 tx lanes (one half-warp per ty)
#pragma unroll
            for (int off = 8; off > 0; off >>= 1) {
                p0 += __shfl_down_sync(0xffffffffu, p0, off, 16);
                p1 += __shfl_down_sync(0xffffffffu, p1, off, 16);
            }
            if (tx == 0) {
                int cb = ib + ty * 8;
#pragma unroll
                for (int c = 0; c < 4; c++) {
                    atomicAdd(&g_kp[0][cb + c],     (int)((p0 >> (8 * c)) & 255u));
                    atomicAdd(&g_kp[0][cb + 4 + c], (int)((p1 >> (8 * c)) & 255u));
                }
            }
        }
    }

    if (MODE == 0) {
        __syncthreads();
        float* smM = (float*)smX;                       // [JT][16][4] merge scratch
        int base0 = (tx * 2) * 64 + ty * 4;
        smM[base0 + 0] = a00; smM[base0 + 1] = a01; smM[base0 + 2] = a02; smM[base0 + 3] = a03;
        int base1 = (tx * 2 + 1) * 64 + ty * 4;
        smM[base1 + 0] = b00; smM[base1 + 1] = b01; smM[base1 + 2] = b02; smM[base1 + 3] = b03;
        __syncthreads();
        if (id < JT) {
            float m0 = 3.4e38f, m1 = 3.4e38f, m2 = 3.4e38f, m3 = 3.4e38f;
            const float* src = &smM[id * 64];
#pragma unroll
            for (int e = 0; e < 64; e++) ins4(m0, m1, m2, m3, src[e]);
            g_rho_sq[m][j0 + id] = fmaxf(m3, 1e-12f);
        }
    } else {
        atomicAdd(&g_kp[1][r0], cntA0);
        atomicAdd(&g_kp[1][r0 + 1], cntA1);
    }
}

// ---- scalar epilogue ------------------------------------------------------
__global__ void final_kernel(float* __restrict__ out) {
    __shared__ float redf[256];
    __shared__ int   redi[256];
    const int tid = threadIdx.x;
    float vals[2];

    for (int dir = 0; dir < 2; dir++) {
        int ks = 0;
        for (int j = tid; j < NPTS; j += 256) ks += g_kp[dir][j];
        redi[tid] = ks;
        __syncthreads();
        for (int s = 128; s > 0; s >>= 1) {
            if (tid < s) redi[tid] += redi[tid + s];
            __syncthreads();
        }
        float kp_sum = (float)redi[0] + 1e-20f;
        __syncthreads();

        const float cq = 3.0f / 24576.0f;
        float r = 0.f;
        for (int j = tid; j < NPTS; j += 256) {
            float ms = g_rho_sq[dir][j];
            float nu = sqrtf(ms);
            float p2 = nu * nu, p4 = p2 * p2, p8 = p4 * p4;
            float p16 = p8 * p8, p32 = p16 * p16;
            float inv = 1.0f / (p32 + 1e-20f);
            float kp = (float)g_kp[dir][j];
            float p_den = fminf(fmaxf(kp / kp_sum * inv, 1e-20f), 1e10f);
            float q_den = fminf(fmaxf(cq * inv, 1e-20f), 1e10f);
            r += (p_den / q_den) * cq;
        }
        redf[tid] = r;
        __syncthreads();
        for (int s = 128; s > 0; s >>= 1) {
            if (tid < s) redf[tid] += redf[tid + s];
            __syncthreads();
        }
        float value = logf(redf[0]);
        vals[dir] = fmaxf(0.0f, value);
        __syncthreads();
    }
    if (tid == 0) out[0] = fmaxf(vals[0], vals[1]);
}

// ---- launch ---------------------------------------------------------------
extern "C" void kernel_launch(void* const* d_in, const int* in_sizes, int n_in,
                              void* d_out, int out_size) {
    const float* P = (const float*)d_in[0];
    const float* Q = (const float*)d_in[1];
    float* out = (float*)d_out;

    norms_kernel<<<(2 * NPTS + 255) / 256, 256>>>(P, Q);
    pass_kernel<0><<<dim3(NPTS / JT, 1, 2), NTHREADS>>>(P, Q);   // knn both dirs
    pass_kernel<1><<<dim3(NPTS / JT, 1, 1), NTHREADS>>>(P, Q);   // merged counts
    final_kernel<<<1, 256>>>(out);
}

// round 3
// speedup vs baseline: 1.6663x; 1.6663x over previous
#include <cuda_runtime.h>
#include <cuda_fp16.h>
#include <math.h>

#define NPTS 8192
#define DIM 32
#define NT 16            // k-pair steps (DIM/2)
#define JT 32            // owner rows per block
#define IT 128           // streamed cols per tile
#define NTHREADS 256

__device__ float g_norm[2][NPTS];     // [0]=P norms, [1]=Q norms
__device__ float g_rho_sq[2][NPTS];   // [0]: Y=Q, [1]: Y=P
__device__ int   g_kp[2][NPTS];
__device__ __align__(16) __half g_h[2][NPTS][DIM];   // fp16 copies of P,Q

__device__ __forceinline__ void ins4(float& m0, float& m1, float& m2, float& m3, float s) {
    if (s < m3) {
        m3 = s;
        float t;
        if (m3 < m2) { t = m2; m2 = m3; m3 = t; }
        if (m2 < m1) { t = m1; m1 = m2; m2 = t; }
        if (m1 < m0) { t = m0; m0 = m1; m1 = t; }
    }
}

// ---- prep: norms (fp32), fp16 conversion, zero counts ---------------------
__global__ void prep_kernel(const float* __restrict__ P, const float* __restrict__ Q) {
    int t = blockIdx.x * blockDim.x + threadIdx.x;
    if (t >= 2 * NPTS) return;
    int w = (t >= NPTS);
    int row = w ? t - NPTS : t;
    const float4* r4 = (const float4*)((w ? Q : P) + (size_t)row * DIM);
    float s = 0.f;
    __half2 h[NT];
#pragma unroll
    for (int i = 0; i < DIM / 4; i++) {
        float4 v = r4[i];
        s = fmaf(v.x, v.x, s);
        s = fmaf(v.y, v.y, s);
        s = fmaf(v.z, v.z, s);
        s = fmaf(v.w, v.w, s);
        h[2 * i]     = __floats2half2_rn(v.x, v.y);
        h[2 * i + 1] = __floats2half2_rn(v.z, v.w);
    }
    g_norm[w][row] = s;
    g_kp[w][row] = 0;
    uint4* dst = (uint4*)g_h[w][row];
    const uint4* srcv = (const uint4*)h;
#pragma unroll
    for (int i = 0; i < 4; i++) dst[i] = srcv[i];
}

// ---- main tiled pass ------------------------------------------------------
// MODE 0: knn (Y vs Y, blockIdx.z = m; m=0 -> Y=Q, m=1 -> Y=P), writes g_rho_sq
// MODE 1: merged count pass over D(P,Q): row counts -> g_kp[1], col counts -> g_kp[0]
template <int MODE>
__global__ __launch_bounds__(NTHREADS, 4)
void pass_kernel() {
    __shared__ __align__(16) __half2 smX[NT][IT];   // 8 KB  [t][i]
    __shared__ __align__(16) __half2 smY[NT][JT];   // 2 KB  [t][j]
    __shared__ float smNB[IT];
    __shared__ float smRB[IT];

    const int id = threadIdx.x;
    const int tx = id & 15;    // 2 owner rows
    const int ty = id >> 4;    // 8 streamed cols

    const int m = (MODE == 0) ? blockIdx.z : 0;
    const int srcY = (MODE == 0) ? (m ? 0 : 1) : 0;   // 0=P, 1=Q in g_h/g_norm
    const int srcX = (MODE == 0) ? srcY : 1;

    const float* __restrict__ nYv = g_norm[srcY];
    const float* __restrict__ nXv = g_norm[srcX];

    const int j0 = blockIdx.x * JT;

    // fill Y tile (k-pair major) once
    if (id < 128) {
        int r = id & 31, h = (id >> 5) & 3;
        uint4 v = ((const uint4*)g_h[srcY][j0 + r])[h];
#pragma unroll
        for (int q = 0; q < 4; q++)
            smY[h * 4 + q][r] = ((const __half2*)&v)[q];
    }

    const int r0 = j0 + tx * 2;
    const float na0 = nYv[r0], na1 = nYv[r0 + 1];

    float a00 = 3.4e38f, a01 = 3.4e38f, a02 = 3.4e38f, a03 = 3.4e38f;
    float b00 = 3.4e38f, b01 = 3.4e38f, b02 = 3.4e38f, b03 = 3.4e38f;
    int cntA0 = 0, cntA1 = 0;
    float rA0 = 0.f, rA1 = 0.f;
    if (MODE == 1) { rA0 = g_rho_sq[1][r0]; rA1 = g_rho_sq[1][r0 + 1]; }

    for (int ib = 0; ib < NPTS; ib += IT) {
        __syncthreads();
        {
            int i = id & 127, h0 = (id >> 7) * 2;
#pragma unroll
            for (int hh = 0; hh < 2; hh++) {
                uint4 v = ((const uint4*)g_h[srcX][ib + i])[h0 + hh];
#pragma unroll
                for (int q = 0; q < 4; q++)
                    smX[(h0 + hh) * 4 + q][i] = ((const __half2*)&v)[q];
            }
            if (id < IT) smNB[id] = nXv[ib + id];
            else if (MODE == 1) smRB[id - IT] = g_rho_sq[0][ib + id - IT];
        }
        __syncthreads();

        __half2 acc[16];
#pragma unroll
        for (int e = 0; e < 16; e++) acc[e] = __float2half2_rn(0.f);

#pragma unroll
        for (int t = 0; t < NT; t++) {
            __half2 y0 = smY[t][tx * 2];
            __half2 y1 = smY[t][tx * 2 + 1];
            uint4 xa = *(const uint4*)&smX[t][ty * 8];
            uint4 xb = *(const uint4*)&smX[t][ty * 8 + 4];
            const __half2* xs0 = (const __half2*)&xa;
            const __half2* xs1 = (const __half2*)&xb;
#pragma unroll
            for (int c = 0; c < 4; c++) {
                acc[c]      = __hfma2(y0, xs0[c], acc[c]);
                acc[4 + c]  = __hfma2(y0, xs1[c], acc[4 + c]);
                acc[8 + c]  = __hfma2(y1, xs0[c], acc[8 + c]);
                acc[12 + c] = __hfma2(y1, xs1[c], acc[12 + c]);
            }
        }

        float nb[8];
        {
            float4 u = *(const float4*)&smNB[ty * 8];
            float4 v = *(const float4*)&smNB[ty * 8 + 4];
            nb[0] = u.x; nb[1] = u.y; nb[2] = u.z; nb[3] = u.w;
            nb[4] = v.x; nb[5] = v.y; nb[6] = v.z; nb[7] = v.w;
        }
        float s0[8], s1[8];
#pragma unroll
        for (int c = 0; c < 8; c++) {
            int ai = (c < 4) ? c : (4 + (c - 4));
            float d0 = __low2float(acc[ai]) + __high2float(acc[ai]);
            s0[c] = fmaf(d0, -2.f, na0 + nb[c]);
            float d1 = __low2float(acc[8 + ai]) + __high2float(acc[8 + ai]);
            s1[c] = fmaf(d1, -2.f, na1 + nb[c]);
        }

        if (MODE == 0) {
#pragma unroll
            for (int c = 0; c < 8; c++) {
                ins4(a00, a01, a02, a03, s0[c]);
                ins4(b00, b01, b02, b03, s1[c]);
            }
        } else {
            float rb[8];
            {
                float4 u = *(const float4*)&smRB[ty * 8];
                float4 v = *(const float4*)&smRB[ty * 8 + 4];
                rb[0] = u.x; rb[1] = u.y; rb[2] = u.z; rb[3] = u.w;
                rb[4] = v.x; rb[5] = v.y; rb[6] = v.z; rb[7] = v.w;
            }
            unsigned int p0 = 0, p1 = 0;
#pragma unroll
            for (int c = 0; c < 4; c++) {
                unsigned int bc = (s0[c] <= rb[c] ? 1u : 0u) + (s1[c] <= rb[c] ? 1u : 0u);
                p0 += bc << (8 * c);
                unsigned int bd = (s0[c + 4] <= rb[c + 4] ? 1u : 0u) + (s1[c + 4] <= rb[c + 4] ? 1u : 0u);
                p1 += bd << (8 * c);
            }
#pragma unroll
            for (int c = 0; c < 8; c++) {
                cntA0 += (s0[c] <= rA0) ? 1 : 0;
                cntA1 += (s1[c] <= rA1) ? 1 : 0;
            }
#pragma unroll
            for (int off = 8; off > 0; off >>= 1) {
                p0 += __shfl_down_sync(0xffffffffu, p0, off, 16);
                p1 += __shfl_down_sync(0xffffffffu, p1, off, 16);
            }
            if (tx == 0) {
                int cb = ib + ty * 8;
#pragma unroll
                for (int c = 0; c < 4; c++) {
                    atomicAdd(&g_kp[0][cb + c],     (int)((p0 >> (8 * c)) & 255u));
                    atomicAdd(&g_kp[0][cb + 4 + c], (int)((p1 >> (8 * c)) & 255u));
                }
            }
        }
    }

    if (MODE == 0) {
        __syncthreads();
        float* smM = (float*)smX;                       // 8 KB = JT*64 floats exactly
        int base0 = (tx * 2) * 64 + ty * 4;
        smM[base0 + 0] = a00; smM[base0 + 1] = a01; smM[base0 + 2] = a02; smM[base0 + 3] = a03;
        int base1 = (tx * 2 + 1) * 64 + ty * 4;
        smM[base1 + 0] = b00; smM[base1 + 1] = b01; smM[base1 + 2] = b02; smM[base1 + 3] = b03;
        __syncthreads();
        if (id < JT) {
            float m0 = 3.4e38f, m1 = 3.4e38f, m2 = 3.4e38f, m3 = 3.4e38f;
            const float* src = &smM[id * 64];
#pragma unroll
            for (int e = 0; e < 64; e++) ins4(m0, m1, m2, m3, src[e]);
            g_rho_sq[m][j0 + id] = fmaxf(m3, 1e-12f);
        }
    } else {
        atomicAdd(&g_kp[1][r0], cntA0);
        atomicAdd(&g_kp[1][r0 + 1], cntA1);
    }
}

// ---- scalar epilogue ------------------------------------------------------
#define FNT 1024
__global__ void final_kernel(float* __restrict__ out) {
    __shared__ float redf[FNT];
    __shared__ int   redi[FNT];
    const int tid = threadIdx.x;
    float vals[2];

    for (int dir = 0; dir < 2; dir++) {
        int ks = 0;
        for (int j = tid; j < NPTS; j += FNT) ks += g_kp[dir][j];
        redi[tid] = ks;
        __syncthreads();
        for (int s = FNT / 2; s > 0; s >>= 1) {
            if (tid < s) redi[tid] += redi[tid + s];
            __syncthreads();
        }
        float kp_sum = (float)redi[0] + 1e-20f;
        __syncthreads();

        const float cq = 3.0f / 24576.0f;
        float r = 0.f;
        for (int j = tid; j < NPTS; j += FNT) {
            float ms = g_rho_sq[dir][j];
            float nu = sqrtf(ms);
            float p2 = nu * nu, p4 = p2 * p2, p8 = p4 * p4;
            float p16 = p8 * p8, p32 = p16 * p16;
            float inv = 1.0f / (p32 + 1e-20f);
            float kp = (float)g_kp[dir][j];
            float p_den = fminf(fmaxf(kp / kp_sum * inv, 1e-20f), 1e10f);
            float q_den = fminf(fmaxf(cq * inv, 1e-20f), 1e10f);
            r += (p_den / q_den) * cq;
        }
        redf[tid] = r;
        __syncthreads();
        for (int s = FNT / 2; s > 0; s >>= 1) {
            if (tid < s) redf[tid] += redf[tid + s];
            __syncthreads();
        }
        float value = logf(redf[0]);
        vals[dir] = fmaxf(0.0f, value);
        __syncthreads();
    }
    if (tid == 0) out[0] = fmaxf(vals[0], vals[1]);
}

// ---- launch ---------------------------------------------------------------
extern "C" void kernel_launch(void* const* d_in, const int* in_sizes, int n_in,
                              void* d_out, int out_size) {
    const float* P = (const float*)d_in[0];
    const float* Q = (const float*)d_in[1];
    float* out = (float*)d_out;

    prep_kernel<<<(2 * NPTS + 255) / 256, 256>>>(P, Q);
    pass_kernel<0><<<dim3(NPTS / JT, 1, 2), NTHREADS>>>();   // knn both dirs
    pass_kernel<1><<<dim3(NPTS / JT, 1, 1), NTHREADS>>>();   // merged counts
    final_kernel<<<1, FNT>>>(out);
}

// round 5
// speedup vs baseline: 1.9893x; 1.1939x over previous
#include <cuda_runtime.h>
#include <cuda_bf16.h>
#include <math.h>
#include <stdint.h>

#define NPTS 8192
#define DIM 32
#define ROWW 64              // padded bf16 slots per global row (128 B)
#define MB 64                // owner rows per block
#define NCHUNK 128           // streamed rows per tile
#define NCH (NPTS / NCHUNK)  // 64
#define BROW 112             // padded SMEM bytes per B row (conflict-free)

__device__ float g_rho_sq[2][NPTS];   // [0]: Y=Q, [1]: Y=P
__device__ int   g_kp[2][NPTS];
__device__ __align__(16) __nv_bfloat16 g_bA[2][NPTS][ROWW];  // [-2x, 1, |x|^2, 0...]
__device__ __align__(16) __nv_bfloat16 g_bB[2][NPTS][ROWW];  // [  x, |x|^2, 1, 0...]

__device__ __forceinline__ void mma16816(float* c, const uint32_t* a, uint32_t b0, uint32_t b1) {
    asm volatile(
        "mma.sync.aligned.m16n8k16.row.col.f32.bf16.bf16.f32 "
        "{%0,%1,%2,%3}, {%4,%5,%6,%7}, {%8,%9}, {%0,%1,%2,%3};"
        : "+f"(c[0]), "+f"(c[1]), "+f"(c[2]), "+f"(c[3])
        : "r"(a[0]), "r"(a[1]), "r"(a[2]), "r"(a[3]), "r"(b0), "r"(b1));
}
__device__ __forceinline__ void ins4(float& m0, float& m1, float& m2, float& m3, float s) {
    if (s < m3) {
        m3 = s;
        float t;
        if (m3 < m2) { t = m2; m2 = m3; m3 = t; }
        if (m2 < m1) { t = m1; m1 = m2; m2 = t; }
        if (m1 < m0) { t = m0; m0 = m1; m1 = t; }
    }
}

// ---------------- prep: build augmented bf16 rows --------------------------
__global__ void prep_kernel(const float* __restrict__ P, const float* __restrict__ Q) {
    int t = blockIdx.x * blockDim.x + threadIdx.x;
    if (t >= 2 * NPTS) return;
    int w = (t >= NPTS);
    int row = w ? t - NPTS : t;
    const float4* r4 = (const float4*)((w ? Q : P) + (size_t)row * DIM);
    float v[DIM];
    float na = 0.f;
#pragma unroll
    for (int i = 0; i < DIM / 4; i++) {
        float4 x = r4[i];
        v[4 * i] = x.x; v[4 * i + 1] = x.y; v[4 * i + 2] = x.z; v[4 * i + 3] = x.w;
        na = fmaf(x.x, x.x, na); na = fmaf(x.y, x.y, na);
        na = fmaf(x.z, x.z, na); na = fmaf(x.w, x.w, na);
    }
    __nv_bfloat16 ra[ROWW], rb[ROWW];
#pragma unroll
    for (int j = 0; j < DIM; j++) {
        ra[j] = __float2bfloat16(-2.f * v[j]);
        rb[j] = __float2bfloat16(v[j]);
    }
#pragma unroll
    for (int j = DIM; j < ROWW; j++) { ra[j] = __float2bfloat16(0.f); rb[j] = __float2bfloat16(0.f); }
    ra[32] = __float2bfloat16(1.f);  ra[33] = __float2bfloat16(na);
    rb[32] = __float2bfloat16(na);   rb[33] = __float2bfloat16(1.f);
    uint4* da = (uint4*)g_bA[w][row];
    uint4* db = (uint4*)g_bB[w][row];
#pragma unroll
    for (int q = 0; q < 8; q++) { da[q] = ((uint4*)ra)[q]; db[q] = ((uint4*)rb)[q]; }
}

// ---------------- main HMMA pass -------------------------------------------
// MODE 0 (knn):   sel=0 -> Y=Q writes rho[0];  sel=1 -> Y=P writes rho[1]
// MODE 1 (count): sel=0 -> owners Q, stream P, rho[0] -> kp[0]; sel=1 -> swap -> kp[1]
template <int MODE>
__global__ void __launch_bounds__(128) mma_pass() {
    __shared__ __align__(16) unsigned char smB[2][NCHUNK * BROW];   // 28 KB

    const int tid = threadIdx.x;
    const int w = tid >> 5;
    const int lane = tid & 31;
    const int g = lane >> 2;        // 0..7
    const int lam = lane & 3;       // 0..3
    const int sel = blockIdx.y;
    const int setA = sel ? 0 : 1;
    const int setB = (MODE == 0) ? setA : (1 - setA);

    const int r0 = blockIdx.x * MB + w * 16 + g;   // this thread's rows: r0, r0+8

    // ---- A fragments, 3 k-steps, held in registers for the whole pass
    uint32_t A[3][4];
    {
        const unsigned char* ab = (const unsigned char*)g_bA[setA] + (size_t)r0 * 128;
#pragma unroll
        for (int ks = 0; ks < 3; ks++) {
            int off = ks * 32 + 4 * lam;
            A[ks][0] = *(const uint32_t*)(ab + off);
            A[ks][1] = *(const uint32_t*)(ab + 8 * 128 + off);
            A[ks][2] = *(const uint32_t*)(ab + off + 16);
            A[ks][3] = *(const uint32_t*)(ab + 8 * 128 + off + 16);
        }
    }

    float rho0 = 0.f, rho1 = 0.f;
    if (MODE == 1) { rho0 = g_rho_sq[sel][r0]; rho1 = g_rho_sq[sel][r0 + 8]; }

    float m0 = 3.4e38f, m1 = 3.4e38f, m2 = 3.4e38f, m3 = 3.4e38f;   // row r0 top4
    float n0 = 3.4e38f, n1 = 3.4e38f, n2 = 3.4e38f, n3 = 3.4e38f;   // row r0+8
    int cnt0 = 0, cnt1 = 0;

    // ---- B tile staging (thread = one stream row per chunk; 96 B payload)
    uint4 st[6];
    const unsigned char* bbase = (const unsigned char*)g_bB[setB];
    {
        const uint4* src = (const uint4*)(bbase + (size_t)tid * 128);
#pragma unroll
        for (int q = 0; q < 6; q++) st[q] = src[q];
        unsigned char* d = smB[0] + tid * BROW;
#pragma unroll
        for (int q = 0; q < 6; q++) *(uint4*)(d + q * 16) = st[q];
    }
    __syncthreads();

    for (int i = 0; i < NCH; i++) {
        if (i < NCH - 1) {
            const uint4* src = (const uint4*)(bbase + (size_t)((i + 1) * NCHUNK + tid) * 128);
#pragma unroll
            for (int q = 0; q < 6; q++) st[q] = src[q];
        }
        const unsigned char* buf = smB[i & 1];
#pragma unroll 2
        for (int nt = 0; nt < NCHUNK / 8; nt++) {
            float c[4] = {0.f, 0.f, 0.f, 0.f};
            const unsigned char* bb = buf + (nt * 8 + g) * BROW + 4 * lam;
#pragma unroll
            for (int ks = 0; ks < 3; ks++) {
                uint32_t b0 = *(const uint32_t*)(bb + ks * 32);
                uint32_t b1 = *(const uint32_t*)(bb + ks * 32 + 16);
                mma16816(c, A[ks], b0, b1);
            }
            if (MODE == 0) {
                ins4(m0, m1, m2, m3, c[0]);
                ins4(m0, m1, m2, m3, c[1]);
                ins4(n0, n1, n2, n3, c[2]);
                ins4(n0, n1, n2, n3, c[3]);
            } else {
                cnt0 += (c[0] <= rho0) ? 1 : 0;
                cnt0 += (c[1] <= rho0) ? 1 : 0;
                cnt1 += (c[2] <= rho1) ? 1 : 0;
                cnt1 += (c[3] <= rho1) ? 1 : 0;
            }
        }
        __syncthreads();
        if (i < NCH - 1) {
            unsigned char* d = smB[(i + 1) & 1] + tid * BROW;
#pragma unroll
            for (int q = 0; q < 6; q++) *(uint4*)(d + q * 16) = st[q];
        }
        __syncthreads();
    }

    // ---- merge across the 4 lambda-lanes sharing each row
    if (MODE == 0) {
#pragma unroll
        for (int d = 1; d <= 2; d <<= 1) {
            float t0 = __shfl_xor_sync(0xffffffffu, m0, d);
            float t1 = __shfl_xor_sync(0xffffffffu, m1, d);
            float t2 = __shfl_xor_sync(0xffffffffu, m2, d);
            float t3 = __shfl_xor_sync(0xffffffffu, m3, d);
            ins4(m0, m1, m2, m3, t0); ins4(m0, m1, m2, m3, t1);
            ins4(m0, m1, m2, m3, t2); ins4(m0, m1, m2, m3, t3);
            float u0 = __shfl_xor_sync(0xffffffffu, n0, d);
            float u1 = __shfl_xor_sync(0xffffffffu, n1, d);
            float u2 = __shfl_xor_sync(0xffffffffu, n2, d);
            float u3 = __shfl_xor_sync(0xffffffffu, n3, d);
            ins4(n0, n1, n2, n3, u0); ins4(n0, n1, n2, n3, u1);
            ins4(n0, n1, n2, n3, u2); ins4(n0, n1, n2, n3, u3);
        }
        if (lam == 0) {
            g_rho_sq[sel][r0]     = fmaxf(m3, 1e-12f);
            g_rho_sq[sel][r0 + 8] = fmaxf(n3, 1e-12f);
        }
    } else {
        cnt0 += __shfl_xor_sync(0xffffffffu, cnt0, 1);
        cnt0 += __shfl_xor_sync(0xffffffffu, cnt0, 2);
        cnt1 += __shfl_xor_sync(0xffffffffu, cnt1, 1);
        cnt1 += __shfl_xor_sync(0xffffffffu, cnt1, 2);
        if (lam == 0) {
            g_kp[sel][r0]     = cnt0;
            g_kp[sel][r0 + 8] = cnt1;
        }
    }
}

// ---------------- scalar epilogue ------------------------------------------
__global__ void final_kernel(float* __restrict__ out) {
    __shared__ int   si[2][8];
    __shared__ float sf[2][8];
    const int tid = threadIdx.x, lane = tid & 31, wp = tid >> 5;

    int ks0 = 0, ks1 = 0;
    for (int j = tid; j < NPTS; j += 256) { ks0 += g_kp[0][j]; ks1 += g_kp[1][j]; }
#pragma unroll
    for (int d = 16; d; d >>= 1) {
        ks0 += __shfl_xor_sync(0xffffffffu, ks0, d);
        ks1 += __shfl_xor_sync(0xffffffffu, ks1, d);
    }
    if (lane == 0) { si[0][wp] = ks0; si[1][wp] = ks1; }
    __syncthreads();
    float kpsum[2];
    {
        int t0 = 0, t1 = 0;
#pragma unroll
        for (int q = 0; q < 8; q++) { t0 += si[0][q]; t1 += si[1][q]; }
        kpsum[0] = (float)t0 + 1e-20f;
        kpsum[1] = (float)t1 + 1e-20f;
    }

    const float cq = 3.0f / 24576.0f;
    float r0 = 0.f, r1 = 0.f;
#pragma unroll
    for (int dir = 0; dir < 2; dir++) {
        float acc = 0.f;
        for (int j = tid; j < NPTS; j += 256) {
            float ms = g_rho_sq[dir][j];
            float nu = sqrtf(ms);
            float p2 = nu * nu, p4 = p2 * p2, p8 = p4 * p4;
            float p16 = p8 * p8, p32 = p16 * p16;
            float inv = 1.0f / (p32 + 1e-20f);
            float kp = (float)g_kp[dir][j];
            float p_den = fminf(fmaxf(kp / kpsum[dir] * inv, 1e-20f), 1e10f);
            float q_den = fminf(fmaxf(cq * inv, 1e-20f), 1e10f);
            acc += (p_den / q_den) * cq;
        }
        if (dir == 0) r0 = acc; else r1 = acc;
    }
#pragma unroll
    for (int d = 16; d; d >>= 1) {
        r0 += __shfl_xor_sync(0xffffffffu, r0, d);
        r1 += __shfl_xor_sync(0xffffffffu, r1, d);
    }
    if (lane == 0) { sf[0][wp] = r0; sf[1][wp] = r1; }
    __syncthreads();
    if (tid == 0) {
        float a0 = 0.f, a1 = 0.f;
#pragma unroll
        for (int q = 0; q < 8; q++) { a0 += sf[0][q]; a1 += sf[1][q]; }
        float v0 = fmaxf(0.0f, logf(a0));
        float v1 = fmaxf(0.0f, logf(a1));
        out[0] = fmaxf(v0, v1);
    }
}

// ---------------- launch ----------------------------------------------------
extern "C" void kernel_launch(void* const* d_in, const int* in_sizes, int n_in,
                              void* d_out, int out_size) {
    const float* P = (const float*)d_in[0];
    const float* Q = (const float*)d_in[1];
    float* out = (float*)d_out;

    prep_kernel<<<(2 * NPTS + 255) / 256, 256>>>(P, Q);
    mma_pass<0><<<dim3(NPTS / MB, 2), 128>>>();   // knn, both directions
    mma_pass<1><<<dim3(NPTS / MB, 2), 128>>>();   // counts, both directions
    final_kernel<<<1, 256>>>(out);
}

// round 6
// speedup vs baseline: 2.8532x; 1.4343x over previous
#include <cuda_runtime.h>
#include <cuda_bf16.h>
#include <math.h>
#include <stdint.h>

#define NPTS 8192
#define DIM 32
#define MB 32                // owner rows per block
#define S 4                  // column splits per block
#define SPLITC 2048          // cols per split
#define CHUNK 64             // rows per staged chunk
#define NCHK (SPLITC / CHUNK)   // 32
#define NTPC (CHUNK / 8)        // 8
#define BROW 80              // padded SMEM bytes per B row (conflict-free)
#define NELEM (S * (CHUNK * 4 + CHUNK / 4))   // staged uint4 per chunk = 4*(256+16)=1088
#define PERSPLIT (CHUNK * 4 + CHUNK / 4)      // 272

__device__ float g_rho_sq[2][NPTS];   // [0]: Y=Q, [1]: Y=P
__device__ int   g_kp[2][NPTS];
__device__ float g_part[2][16];
__device__ __align__(16) float g_nrm[2][NPTS];
__device__ __align__(16) __nv_bfloat16 g_bA[2][NPTS][DIM];  // -2x (bf16)
__device__ __align__(16) __nv_bfloat16 g_bB[2][NPTS][DIM];  //   x (bf16)

__device__ __forceinline__ void mma16816(float* c, const uint32_t* a, uint32_t b0, uint32_t b1) {
    asm volatile(
        "mma.sync.aligned.m16n8k16.row.col.f32.bf16.bf16.f32 "
        "{%0,%1,%2,%3}, {%4,%5,%6,%7}, {%8,%9}, {%0,%1,%2,%3};"
        : "+f"(c[0]), "+f"(c[1]), "+f"(c[2]), "+f"(c[3])
        : "r"(a[0]), "r"(a[1]), "r"(a[2]), "r"(a[3]), "r"(b0), "r"(b1));
}
__device__ __forceinline__ void ins4(float& m0, float& m1, float& m2, float& m3, float s) {
    if (s < m3) {
        m3 = s;
        float t;
        if (m3 < m2) { t = m2; m2 = m3; m3 = t; }
        if (m2 < m1) { t = m1; m1 = m2; m2 = t; }
        if (m1 < m0) { t = m0; m0 = m1; m1 = t; }
    }
}

// ---------------- prep ------------------------------------------------------
__global__ void prep_kernel(const float* __restrict__ P, const float* __restrict__ Q) {
    int t = blockIdx.x * blockDim.x + threadIdx.x;
    if (t >= 2 * NPTS) return;
    int w = (t >= NPTS);
    int row = w ? t - NPTS : t;
    const float4* r4 = (const float4*)((w ? Q : P) + (size_t)row * DIM);
    float na = 0.f;
    __nv_bfloat16 ra[DIM], rb[DIM];
#pragma unroll
    for (int i = 0; i < DIM / 4; i++) {
        float4 x = r4[i];
        na = fmaf(x.x, x.x, na); na = fmaf(x.y, x.y, na);
        na = fmaf(x.z, x.z, na); na = fmaf(x.w, x.w, na);
        ra[4 * i]     = __float2bfloat16(-2.f * x.x);
        ra[4 * i + 1] = __float2bfloat16(-2.f * x.y);
        ra[4 * i + 2] = __float2bfloat16(-2.f * x.z);
        ra[4 * i + 3] = __float2bfloat16(-2.f * x.w);
        rb[4 * i]     = __float2bfloat16(x.x);
        rb[4 * i + 1] = __float2bfloat16(x.y);
        rb[4 * i + 2] = __float2bfloat16(x.z);
        rb[4 * i + 3] = __float2bfloat16(x.w);
    }
    g_nrm[w][row] = na;
    g_kp[w][row] = 0;
    uint4* da = (uint4*)g_bA[w][row];
    uint4* db = (uint4*)g_bB[w][row];
#pragma unroll
    for (int q = 0; q < 4; q++) { da[q] = ((uint4*)ra)[q]; db[q] = ((uint4*)rb)[q]; }
}

// ---------------- main HMMA pass -------------------------------------------
// MODE 0 (knn):   sel=0 -> Y=Q writes rho[0];  sel=1 -> Y=P writes rho[1]
// MODE 1 (count): sel=0 -> owners Q, stream P -> kp[0]; sel=1 -> swap -> kp[1]
template <int MODE>
__global__ void __launch_bounds__(256) mma_pass() {
    __shared__ __align__(16) unsigned char smD[2][S][CHUNK * BROW];  // 40 KB
    __shared__ __align__(16) float smN[2][S][CHUNK];                 //  2 KB

    const int tid = threadIdx.x;
    const int w = tid >> 5, lane = tid & 31;
    const int g = lane >> 2, lam = lane & 3;
    const int rg = w & 1, sp = w >> 1;
    const int sel = blockIdx.y;
    const int setA = sel ? 0 : 1;
    const int setB = (MODE == 0) ? setA : 1 - setA;
    const int r0 = blockIdx.x * MB + rg * 16 + g;   // rows r0, r0+8

    // A fragments (K=32 -> 2 ksteps), register-resident
    uint32_t A[2][4];
    {
        const unsigned char* ab = (const unsigned char*)g_bA[setA] + (size_t)r0 * 64;
#pragma unroll
        for (int ks = 0; ks < 2; ks++) {
            int off = ks * 32 + 4 * lam;
            A[ks][0] = *(const uint32_t*)(ab + off);
            A[ks][1] = *(const uint32_t*)(ab + 8 * 64 + off);
            A[ks][2] = *(const uint32_t*)(ab + off + 16);
            A[ks][3] = *(const uint32_t*)(ab + 8 * 64 + off + 16);
        }
    }
    const float na0 = g_nrm[setA][r0], na1 = g_nrm[setA][r0 + 8];
    float th0 = 0.f, th1 = 0.f;
    if (MODE == 1) {
        th0 = g_rho_sq[sel][r0] - na0;
        th1 = g_rho_sq[sel][r0 + 8] - na1;
    }

    float m0 = 3.4e38f, m1 = 3.4e38f, m2 = 3.4e38f, m3 = 3.4e38f;
    float n0 = 3.4e38f, n1 = 3.4e38f, n2 = 3.4e38f, n3 = 3.4e38f;
    int cnt0 = 0, cnt1 = 0;

    const unsigned char* bB = (const unsigned char*)g_bB[setB];

    // ---- stage chunk 0
    for (int e = tid; e < NELEM; e += 256) {
        int spe = e / PERSPLIT, r = e % PERSPLIT;
        uint4 v;
        if (r < CHUNK * 4) {
            int row = r >> 2, q = r & 3;
            v = *(const uint4*)(bB + (size_t)(spe * SPLITC + row) * 64 + q * 16);
            *(uint4*)(&smD[0][spe][row * BROW + q * 16]) = v;
        } else {
            int nr = r - CHUNK * 4;
            v = *(const uint4*)((const unsigned char*)(g_nrm[setB] + spe * SPLITC) + nr * 16);
            *(uint4*)((unsigned char*)smN[0][spe] + nr * 16) = v;
        }
    }
    __syncthreads();

    for (int ci = 0; ci < NCHK; ci++) {
        // prefetch next chunk into registers
        uint4 pf[5];
        if (ci < NCHK - 1) {
#pragma unroll
            for (int it = 0; it < 5; it++) {
                int e = tid + it * 256;
                if (e < NELEM) {
                    int spe = e / PERSPLIT, r = e % PERSPLIT;
                    if (r < CHUNK * 4) {
                        int row = r >> 2, q = r & 3;
                        pf[it] = *(const uint4*)(bB + (size_t)(spe * SPLITC + (ci + 1) * CHUNK + row) * 64 + q * 16);
                    } else {
                        int nr = r - CHUNK * 4;
                        pf[it] = *(const uint4*)((const unsigned char*)(g_nrm[setB] + spe * SPLITC + (ci + 1) * CHUNK) + nr * 16);
                    }
                }
            }
        }

        const unsigned char* buf = smD[ci & 1][sp];
        const float* nrm = smN[ci & 1][sp];
#pragma unroll
        for (int nt = 0; nt < NTPC; nt++) {
            float c[4] = {0.f, 0.f, 0.f, 0.f};
            const unsigned char* bb = buf + (nt * 8 + g) * BROW + 4 * lam;
#pragma unroll
            for (int ks = 0; ks < 2; ks++)
                mma16816(c, A[ks], *(const uint32_t*)(bb + ks * 32),
                                   *(const uint32_t*)(bb + ks * 32 + 16));
            float2 nb = *(const float2*)(nrm + nt * 8 + 2 * lam);
            if (MODE == 0) {
                ins4(m0, m1, m2, m3, c[0] + (na0 + nb.x));
                ins4(m0, m1, m2, m3, c[1] + (na0 + nb.y));
                ins4(n0, n1, n2, n3, c[2] + (na1 + nb.x));
                ins4(n0, n1, n2, n3, c[3] + (na1 + nb.y));
            } else {
                cnt0 += (c[0] <= th0 - nb.x) ? 1 : 0;
                cnt0 += (c[1] <= th0 - nb.y) ? 1 : 0;
                cnt1 += (c[2] <= th1 - nb.x) ? 1 : 0;
                cnt1 += (c[3] <= th1 - nb.y) ? 1 : 0;
            }
        }
        __syncthreads();
        if (ci < NCHK - 1) {
            int b = (ci + 1) & 1;
#pragma unroll
            for (int it = 0; it < 5; it++) {
                int e = tid + it * 256;
                if (e < NELEM) {
                    int spe = e / PERSPLIT, r = e % PERSPLIT;
                    if (r < CHUNK * 4) {
                        int row = r >> 2, q = r & 3;
                        *(uint4*)(&smD[b][spe][row * BROW + q * 16]) = pf[it];
                    } else {
                        int nr = r - CHUNK * 4;
                        *(uint4*)((unsigned char*)smN[b][spe] + nr * 16) = pf[it];
                    }
                }
            }
        }
        __syncthreads();
    }

    // ---- merge across the 4 lambda-lanes
    if (MODE == 0) {
#pragma unroll
        for (int d = 1; d <= 2; d <<= 1) {
            float t0 = __shfl_xor_sync(0xffffffffu, m0, d);
            float t1 = __shfl_xor_sync(0xffffffffu, m1, d);
            float t2 = __shfl_xor_sync(0xffffffffu, m2, d);
            float t3 = __shfl_xor_sync(0xffffffffu, m3, d);
            ins4(m0, m1, m2, m3, t0); ins4(m0, m1, m2, m3, t1);
            ins4(m0, m1, m2, m3, t2); ins4(m0, m1, m2, m3, t3);
            float u0 = __shfl_xor_sync(0xffffffffu, n0, d);
            float u1 = __shfl_xor_sync(0xffffffffu, n1, d);
            float u2 = __shfl_xor_sync(0xffffffffu, n2, d);
            float u3 = __shfl_xor_sync(0xffffffffu, n3, d);
            ins4(n0, n1, n2, n3, u0); ins4(n0, n1, n2, n3, u1);
            ins4(n0, n1, n2, n3, u2); ins4(n0, n1, n2, n3, u3);
        }
        // cross-split merge in smem
        __syncthreads();
        float* smM = (float*)smD;   // [S][MB][4]
        if (lam == 0) {
            float* d0 = &smM[(sp * MB + rg * 16 + g) * 4];
            d0[0] = m0; d0[1] = m1; d0[2] = m2; d0[3] = m3;
            float* d1 = &smM[(sp * MB + rg * 16 + g + 8) * 4];
            d1[0] = n0; d1[1] = n1; d1[2] = n2; d1[3] = n3;
        }
        __syncthreads();
        if (tid < MB) {
            float q0 = 3.4e38f, q1 = 3.4e38f, q2 = 3.4e38f, q3 = 3.4e38f;
#pragma unroll
            for (int spq = 0; spq < S; spq++) {
                const float* src = &smM[(spq * MB + tid) * 4];
                ins4(q0, q1, q2, q3, src[0]); ins4(q0, q1, q2, q3, src[1]);
                ins4(q0, q1, q2, q3, src[2]); ins4(q0, q1, q2, q3, src[3]);
            }
            g_rho_sq[sel][blockIdx.x * MB + tid] = fmaxf(q3, 1e-12f);
        }
    } else {
        cnt0 += __shfl_xor_sync(0xffffffffu, cnt0, 1);
        cnt0 += __shfl_xor_sync(0xffffffffu, cnt0, 2);
        cnt1 += __shfl_xor_sync(0xffffffffu, cnt1, 1);
        cnt1 += __shfl_xor_sync(0xffffffffu, cnt1, 2);
        if (lam == 0) {
            atomicAdd(&g_kp[sel][r0], cnt0);
            atomicAdd(&g_kp[sel][r0 + 8], cnt1);
        }
    }
}

// ---------------- final reduction (two-stage) ------------------------------
__global__ void final1_kernel() {
    __shared__ int si[2][8];
    const int b = blockIdx.x, tid = threadIdx.x, lane = tid & 31, wp = tid >> 5;
    int s0 = 0, s1 = 0;
    for (int j = b * 512 + tid; j < (b + 1) * 512; j += 256) {
        s0 += g_kp[0][j]; s1 += g_kp[1][j];
    }
#pragma unroll
    for (int d = 16; d; d >>= 1) {
        s0 += __shfl_xor_sync(0xffffffffu, s0, d);
        s1 += __shfl_xor_sync(0xffffffffu, s1, d);
    }
    if (lane == 0) { si[0][wp] = s0; si[1][wp] = s1; }
    __syncthreads();
    if (tid == 0) {
        int t0 = 0, t1 = 0;
#pragma unroll
        for (int q = 0; q < 8; q++) { t0 += si[0][q]; t1 += si[1][q]; }
        g_part[0][b] = (float)t0;
        g_part[1][b] = (float)t1;
    }
}

__global__ void final2_kernel(float* __restrict__ out) {
    __shared__ float sf[2][32];
    const int tid = threadIdx.x, lane = tid & 31, wp = tid >> 5;
    float kpsum[2];
#pragma unroll
    for (int dir = 0; dir < 2; dir++) {
        float s = 0.f;
#pragma unroll
        for (int q = 0; q < 16; q++) s += g_part[dir][q];
        kpsum[dir] = s + 1e-20f;
    }
    const float cq = 3.0f / 24576.0f;
    float r0 = 0.f, r1 = 0.f;
#pragma unroll
    for (int dir = 0; dir < 2; dir++) {
        float acc = 0.f;
        for (int j = tid; j < NPTS; j += 1024) {
            float ms = g_rho_sq[dir][j];
            float nu = sqrtf(ms);
            float p2 = nu * nu, p4 = p2 * p2, p8 = p4 * p4;
            float p16 = p8 * p8, p32 = p16 * p16;
            float inv = 1.0f / (p32 + 1e-20f);
            float kp = (float)g_kp[dir][j];
            float p_den = fminf(fmaxf(kp / kpsum[dir] * inv, 1e-20f), 1e10f);
            float q_den = fminf(fmaxf(cq * inv, 1e-20f), 1e10f);
            acc += (p_den / q_den) * cq;
        }
        if (dir == 0) r0 = acc; else r1 = acc;
    }
#pragma unroll
    for (int d = 16; d; d >>= 1) {
        r0 += __shfl_xor_sync(0xffffffffu, r0, d);
        r1 += __shfl_xor_sync(0xffffffffu, r1, d);
    }
    if (lane == 0) { sf[0][wp] = r0; sf[1][wp] = r1; }
    __syncthreads();
    if (tid == 0) {
        float a0 = 0.f, a1 = 0.f;
#pragma unroll
        for (int q = 0; q < 32; q++) { a0 += sf[0][q]; a1 += sf[1][q]; }
        float v0 = fmaxf(0.0f, logf(a0));
        float v1 = fmaxf(0.0f, logf(a1));
        out[0] = fmaxf(v0, v1);
    }
}

// ---------------- launch ----------------------------------------------------
extern "C" void kernel_launch(void* const* d_in, const int* in_sizes, int n_in,
                              void* d_out, int out_size) {
    const float* P = (const float*)d_in[0];
    const float* Q = (const float*)d_in[1];
    float* out = (float*)d_out;

    prep_kernel<<<(2 * NPTS + 255) / 256, 256>>>(P, Q);
    mma_pass<0><<<dim3(NPTS / MB, 2), 256>>>();   // knn, both directions
    mma_pass<1><<<dim3(NPTS / MB, 2), 256>>>();   // counts, both directions
    final1_kernel<<<16, 256>>>();
    final2_kernel<<<1, 1024>>>(out);
}

// round 7
// speedup vs baseline: 3.9557x; 1.3864x over previous
#include <cuda_runtime.h>
#include <cuda_fp8.h>
#include <math.h>
#include <stdint.h>

#define NPTS 8192
#define DIM 32
#define MB 32                // owner rows per block
#define S 4                  // column splits per block
#define SPLITC 2048          // cols per split
#define CHUNK 64             // rows per staged chunk
#define NCHK (SPLITC / CHUNK)   // 32
#define NTPC (CHUNK / 8)        // 8
#define BROW 48              // padded SMEM bytes per fp8 B row (stride 12 words, conflict-free)

__device__ float g_rho_sq[2][NPTS];   // [0]: Y=Q, [1]: Y=P (includes +na, floored)
__device__ int   g_kp[2][NPTS];
__device__ float g_part[2][16];
__device__ __align__(16) float g_nrm[2][NPTS];
__device__ __align__(16) unsigned char g_bA[2][NPTS][DIM];  // e4m3(-2x)
__device__ __align__(16) unsigned char g_bB[2][NPTS][DIM];  // e4m3(x)

__device__ __forceinline__ void qmma(float* c, const uint32_t* a, uint32_t b0, uint32_t b1) {
    asm volatile(
        "mma.sync.aligned.m16n8k32.row.col.f32.e4m3.e4m3.f32 "
        "{%0,%1,%2,%3}, {%4,%5,%6,%7}, {%8,%9}, {%0,%1,%2,%3};"
        : "+f"(c[0]), "+f"(c[1]), "+f"(c[2]), "+f"(c[3])
        : "r"(a[0]), "r"(a[1]), "r"(a[2]), "r"(a[3]), "r"(b0), "r"(b1));
}
__device__ __forceinline__ void ins4(float& m0, float& m1, float& m2, float& m3, float s) {
    if (s < m3) {
        m3 = s;
        float t;
        if (m3 < m2) { t = m2; m2 = m3; m3 = t; }
        if (m2 < m1) { t = m1; m1 = m2; m2 = t; }
        if (m1 < m0) { t = m0; m0 = m1; m1 = t; }
    }
}

// ---------------- prep ------------------------------------------------------
__global__ void prep_kernel(const float* __restrict__ P, const float* __restrict__ Q) {
    int t = blockIdx.x * blockDim.x + threadIdx.x;
    if (t >= 2 * NPTS) return;
    int w = (t >= NPTS);
    int row = w ? t - NPTS : t;
    const float4* r4 = (const float4*)((w ? Q : P) + (size_t)row * DIM);
    float na = 0.f;
    unsigned char ra[DIM], rb[DIM];
#pragma unroll
    for (int i = 0; i < DIM / 4; i++) {
        float4 x = r4[i];
        na = fmaf(x.x, x.x, na); na = fmaf(x.y, x.y, na);
        na = fmaf(x.z, x.z, na); na = fmaf(x.w, x.w, na);
        const float v[4] = {x.x, x.y, x.z, x.w};
#pragma unroll
        for (int e = 0; e < 4; e++) {
            ra[4 * i + e] = __nv_cvt_float_to_fp8(-2.f * v[e], __NV_SATFINITE, __NV_E4M3);
            rb[4 * i + e] = __nv_cvt_float_to_fp8(v[e], __NV_SATFINITE, __NV_E4M3);
        }
    }
    g_nrm[w][row] = na;
    g_kp[w][row] = 0;
    uint4* da = (uint4*)g_bA[w][row];
    uint4* db = (uint4*)g_bB[w][row];
#pragma unroll
    for (int q = 0; q < 2; q++) { da[q] = ((uint4*)ra)[q]; db[q] = ((uint4*)rb)[q]; }
}

// ---------------- main QMMA pass -------------------------------------------
// MODE 0 (knn):   sel=0 -> Y=Q writes rho[0];  sel=1 -> Y=P writes rho[1]
// MODE 1 (count): sel=0 -> owners Q, stream P -> kp[0]; sel=1 -> swap -> kp[1]
template <int MODE>
__global__ void __launch_bounds__(256) mma_pass() {
    __shared__ __align__(16) unsigned char smD[2][S][CHUNK * BROW];  // 24 KB
    __shared__ __align__(16) float smN[2][S][CHUNK];                 //  2 KB

    const int tid = threadIdx.x;
    const int w = tid >> 5, lane = tid & 31;
    const int g = lane >> 2, lam = lane & 3;
    const int rg = w & 1, sp = w >> 1;
    const int sel = blockIdx.y;
    const int setA = sel ? 0 : 1;
    const int setB = (MODE == 0) ? setA : 1 - setA;
    const int r0 = blockIdx.x * MB + rg * 16 + g;   // rows r0, r0+8

    // A fragments (K=32, one kstep), register-resident
    uint32_t A[4];
    {
        const unsigned char* ab = (const unsigned char*)g_bA[setA] + (size_t)r0 * 32 + 4 * lam;
        A[0] = *(const uint32_t*)(ab);
        A[1] = *(const uint32_t*)(ab + 8 * 32);
        A[2] = *(const uint32_t*)(ab + 16);
        A[3] = *(const uint32_t*)(ab + 8 * 32 + 16);
    }
    const float na0 = g_nrm[setA][r0], na1 = g_nrm[setA][r0 + 8];
    float th0 = 0.f, th1 = 0.f;
    if (MODE == 1) {
        th0 = g_rho_sq[sel][r0] - na0;
        th1 = g_rho_sq[sel][r0 + 8] - na1;
    }

    float m0 = 3.4e38f, m1 = 3.4e38f, m2 = 3.4e38f, m3 = 3.4e38f;
    float n0 = 3.4e38f, n1 = 3.4e38f, n2 = 3.4e38f, n3 = 3.4e38f;
    int cnt0 = 0, cnt1 = 0;

    // staging roles: thread = (split sp2, row r)
    const int sp2 = tid >> 6, rr = tid & 63;
    const unsigned char* bB = (const unsigned char*)g_bB[setB] + (size_t)(sp2 * SPLITC + rr) * 32;
    const unsigned char* nB = (const unsigned char*)(g_nrm[setB] + sp2 * SPLITC) + rr * 16;

    // ---- stage chunk 0
    {
        uint4 v0 = *(const uint4*)(bB);
        uint4 v1 = *(const uint4*)(bB + 16);
        *(uint4*)(&smD[0][sp2][rr * BROW])      = v0;
        *(uint4*)(&smD[0][sp2][rr * BROW + 16]) = v1;
        if (rr < 16) *(uint4*)((unsigned char*)smN[0][sp2] + rr * 16) = *(const uint4*)nB;
    }
    __syncthreads();

    for (int ci = 0; ci < NCHK; ci++) {
        uint4 p0, p1, pn;
        if (ci < NCHK - 1) {
            const unsigned char* src = bB + (size_t)(ci + 1) * CHUNK * 32;
            p0 = *(const uint4*)(src);
            p1 = *(const uint4*)(src + 16);
            if (rr < 16) pn = *(const uint4*)(nB + (size_t)(ci + 1) * CHUNK * 4);
        }

        const unsigned char* buf = smD[ci & 1][sp];
        const float* nrm = smN[ci & 1][sp];
#pragma unroll
        for (int nt = 0; nt < NTPC; nt++) {
            float c[4] = {0.f, 0.f, 0.f, 0.f};
            const unsigned char* bb = buf + (nt * 8 + g) * BROW + 4 * lam;
            qmma(c, A, *(const uint32_t*)(bb), *(const uint32_t*)(bb + 16));
            float2 nb = *(const float2*)(nrm + nt * 8 + 2 * lam);
            if (MODE == 0) {
                float s0 = c[0] + nb.x, s1 = c[1] + nb.y;
                if (fminf(s0, s1) < m3) { ins4(m0, m1, m2, m3, s0); ins4(m0, m1, m2, m3, s1); }
                float s2 = c[2] + nb.x, s3 = c[3] + nb.y;
                if (fminf(s2, s3) < n3) { ins4(n0, n1, n2, n3, s2); ins4(n0, n1, n2, n3, s3); }
            } else {
                cnt0 += (c[0] <= th0 - nb.x) ? 1 : 0;
                cnt0 += (c[1] <= th0 - nb.y) ? 1 : 0;
                cnt1 += (c[2] <= th1 - nb.x) ? 1 : 0;
                cnt1 += (c[3] <= th1 - nb.y) ? 1 : 0;
            }
        }
        __syncthreads();
        if (ci < NCHK - 1) {
            int b = (ci + 1) & 1;
            *(uint4*)(&smD[b][sp2][rr * BROW])      = p0;
            *(uint4*)(&smD[b][sp2][rr * BROW + 16]) = p1;
            if (rr < 16) *(uint4*)((unsigned char*)smN[b][sp2] + rr * 16) = pn;
        }
        __syncthreads();
    }

    // ---- merge across the 4 lambda-lanes
    if (MODE == 0) {
#pragma unroll
        for (int d = 1; d <= 2; d <<= 1) {
            float t0 = __shfl_xor_sync(0xffffffffu, m0, d);
            float t1 = __shfl_xor_sync(0xffffffffu, m1, d);
            float t2 = __shfl_xor_sync(0xffffffffu, m2, d);
            float t3 = __shfl_xor_sync(0xffffffffu, m3, d);
            ins4(m0, m1, m2, m3, t0); ins4(m0, m1, m2, m3, t1);
            ins4(m0, m1, m2, m3, t2); ins4(m0, m1, m2, m3, t3);
            float u0 = __shfl_xor_sync(0xffffffffu, n0, d);
            float u1 = __shfl_xor_sync(0xffffffffu, n1, d);
            float u2 = __shfl_xor_sync(0xffffffffu, n2, d);
            float u3 = __shfl_xor_sync(0xffffffffu, n3, d);
            ins4(n0, n1, n2, n3, u0); ins4(n0, n1, n2, n3, u1);
            ins4(n0, n1, n2, n3, u2); ins4(n0, n1, n2, n3, u3);
        }
        __syncthreads();
        float* smM = (float*)smD;   // [S][MB][4]
        if (lam == 0) {
            float* d0 = &smM[(sp * MB + rg * 16 + g) * 4];
            d0[0] = m0; d0[1] = m1; d0[2] = m2; d0[3] = m3;
            float* d1 = &smM[(sp * MB + rg * 16 + g + 8) * 4];
            d1[0] = n0; d1[1] = n1; d1[2] = n2; d1[3] = n3;
        }
        __syncthreads();
        if (tid < MB) {
            float q0 = 3.4e38f, q1 = 3.4e38f, q2 = 3.4e38f, q3 = 3.4e38f;
#pragma unroll
            for (int spq = 0; spq < S; spq++) {
                const float* src = &smM[(spq * MB + tid) * 4];
                ins4(q0, q1, q2, q3, src[0]); ins4(q0, q1, q2, q3, src[1]);
                ins4(q0, q1, q2, q3, src[2]); ins4(q0, q1, q2, q3, src[3]);
            }
            int row = blockIdx.x * MB + tid;
            g_rho_sq[sel][row] = fmaxf(q3 + g_nrm[setA][row], 1e-12f);
        }
    } else {
        cnt0 += __shfl_xor_sync(0xffffffffu, cnt0, 1);
        cnt0 += __shfl_xor_sync(0xffffffffu, cnt0, 2);
        cnt1 += __shfl_xor_sync(0xffffffffu, cnt1, 1);
        cnt1 += __shfl_xor_sync(0xffffffffu, cnt1, 2);
        if (lam == 0) {
            atomicAdd(&g_kp[sel][r0], cnt0);
            atomicAdd(&g_kp[sel][r0 + 8], cnt1);
        }
    }
}

// ---------------- final reduction (two-stage) ------------------------------
__global__ void final1_kernel() {
    __shared__ int si[2][8];
    const int b = blockIdx.x, tid = threadIdx.x, lane = tid & 31, wp = tid >> 5;
    int s0 = 0, s1 = 0;
    for (int j = b * 512 + tid; j < (b + 1) * 512; j += 256) {
        s0 += g_kp[0][j]; s1 += g_kp[1][j];
    }
#pragma unroll
    for (int d = 16; d; d >>= 1) {
        s0 += __shfl_xor_sync(0xffffffffu, s0, d);
        s1 += __shfl_xor_sync(0xffffffffu, s1, d);
    }
    if (lane == 0) { si[0][wp] = s0; si[1][wp] = s1; }
    __syncthreads();
    if (tid == 0) {
        int t0 = 0, t1 = 0;
#pragma unroll
        for (int q = 0; q < 8; q++) { t0 += si[0][q]; t1 += si[1][q]; }
        g_part[0][b] = (float)t0;
        g_part[1][b] = (float)t1;
    }
}

__global__ void final2_kernel(float* __restrict__ out) {
    __shared__ float sf[2][32];
    const int tid = threadIdx.x, lane = tid & 31, wp = tid >> 5;
    float kpsum[2];
#pragma unroll
    for (int dir = 0; dir < 2; dir++) {
        float s = 0.f;
#pragma unroll
        for (int q = 0; q < 16; q++) s += g_part[dir][q];
        kpsum[dir] = s + 1e-20f;
    }
    const float cq = 3.0f / 24576.0f;
    float r0 = 0.f, r1 = 0.f;
#pragma unroll
    for (int dir = 0; dir < 2; dir++) {
        float acc = 0.f;
        for (int j = tid; j < NPTS; j += 1024) {
            float ms = g_rho_sq[dir][j];
            float nu = sqrtf(ms);
            float p2 = nu * nu, p4 = p2 * p2, p8 = p4 * p4;
            float p16 = p8 * p8, p32 = p16 * p16;
            float inv = 1.0f / (p32 + 1e-20f);
            float kp = (float)g_kp[dir][j];
            float p_den = fminf(fmaxf(kp / kpsum[dir] * inv, 1e-20f), 1e10f);
            float q_den = fminf(fmaxf(cq * inv, 1e-20f), 1e10f);
            acc += (p_den / q_den) * cq;
        }
        if (dir == 0) r0 = acc; else r1 = acc;
    }
#pragma unroll
    for (int d = 16; d; d >>= 1) {
        r0 += __shfl_xor_sync(0xffffffffu, r0, d);
        r1 += __shfl_xor_sync(0xffffffffu, r1, d);
    }
    if (lane == 0) { sf[0][wp] = r0; sf[1][wp] = r1; }
    __syncthreads();
    if (tid == 0) {
        float a0 = 0.f, a1 = 0.f;
#pragma unroll
        for (int q = 0; q < 32; q++) { a0 += sf[0][q]; a1 += sf[1][q]; }
        float v0 = fmaxf(0.0f, logf(a0));
        float v1 = fmaxf(0.0f, logf(a1));
        out[0] = fmaxf(v0, v1);
    }
}

// ---------------- launch ----------------------------------------------------
extern "C" void kernel_launch(void* const* d_in, const int* in_sizes, int n_in,
                              void* d_out, int out_size) {
    const float* P = (const float*)d_in[0];
    const float* Q = (const float*)d_in[1];
    float* out = (float*)d_out;

    prep_kernel<<<(2 * NPTS + 255) / 256, 256>>>(P, Q);
    mma_pass<0><<<dim3(NPTS / MB, 2), 256>>>();   // knn, both directions
    mma_pass<1><<<dim3(NPTS / MB, 2), 256>>>();   // counts, both directions
    final1_kernel<<<16, 256>>>();
    final2_kernel<<<1, 1024>>>(out);
}